// round 1
// baseline (speedup 1.0000x reference)
#include <cuda_runtime.h>

#define BATCH 16
#define CHAN  3
#define HEIGHT 512
#define WIDTH  512
#define DELTA2 1e-6f
#define ALPHA  0.45f

__global__ void zero_out_kernel(float* out, int n) {
    int i = blockIdx.x * blockDim.x + threadIdx.x;
    if (i < n) out[i] = 0.0f;
}

__global__ __launch_bounds__(256)
void photometric_kernel(const float* __restrict__ frame1,
                        const float* __restrict__ frame2,
                        const float* __restrict__ flow,
                        float* __restrict__ out) {
    const int HW = HEIGHT * WIDTH;
    const int idx = blockIdx.x * blockDim.x + threadIdx.x;   // pixel id over B*H*W
    const int total = BATCH * HW;

    float acc = 0.0f;
    if (idx < total) {
        const int b  = idx / HW;
        const int hw = idx - b * HW;
        const int y  = hw / WIDTH;
        const int x  = hw - y * WIDTH;

        // flow layout: [B, 2, H, W]
        const float fx = flow[(b * 2 + 0) * HW + hw];
        const float fy = flow[(b * 2 + 1) * HW + hw];

        // ix = clip((x+fx)/W*(W-1), 0, W-1), same for y
        const float sx = (float)(WIDTH  - 1) / (float)WIDTH;
        const float sy = (float)(HEIGHT - 1) / (float)HEIGHT;
        float ix = ((float)x + fx) * sx;
        float iy = ((float)y + fy) * sy;
        ix = fminf(fmaxf(ix, 0.0f), (float)(WIDTH  - 1));
        iy = fminf(fmaxf(iy, 0.0f), (float)(HEIGHT - 1));

        const float x0f = floorf(ix);
        const float y0f = floorf(iy);
        const float wx = ix - x0f;
        const float wy = iy - y0f;
        const int x0 = (int)x0f;
        const int y0 = (int)y0f;
        const int x1 = min(x0 + 1, WIDTH  - 1);
        const int y1 = min(y0 + 1, HEIGHT - 1);

        const int i00 = y0 * WIDTH + x0;
        const int i01 = y0 * WIDTH + x1;
        const int i10 = y1 * WIDTH + x0;
        const int i11 = y1 * WIDTH + x1;

        const float* f1b = frame1 + (size_t)b * CHAN * HW + hw;
        const float* f2b = frame2 + (size_t)b * CHAN * HW;

        #pragma unroll
        for (int c = 0; c < CHAN; c++) {
            const float* p = f2b + c * HW;
            const float v00 = __ldg(p + i00);
            const float v01 = __ldg(p + i01);
            const float v10 = __ldg(p + i10);
            const float v11 = __ldg(p + i11);
            const float top = v00 * (1.0f - wx) + v01 * wx;
            const float bot = v10 * (1.0f - wx) + v11 * wx;
            const float warped = top * (1.0f - wy) + bot * wy;
            const float d = __ldg(f1b + c * HW) - warped;
            const float t = d * d + DELTA2;
            acc += __powf(t, ALPHA);
        }
    }

    // warp reduce
    #pragma unroll
    for (int off = 16; off > 0; off >>= 1)
        acc += __shfl_down_sync(0xFFFFFFFFu, acc, off);

    __shared__ float warp_sums[8];
    const int lane = threadIdx.x & 31;
    const int wid  = threadIdx.x >> 5;
    if (lane == 0) warp_sums[wid] = acc;
    __syncthreads();

    if (wid == 0) {
        float s = (lane < (blockDim.x >> 5)) ? warp_sums[lane] : 0.0f;
        #pragma unroll
        for (int off = 4; off > 0; off >>= 1)
            s += __shfl_down_sync(0xFFFFFFFFu, s, off);
        if (lane == 0) atomicAdd(out, s);
    }
}

extern "C" void kernel_launch(void* const* d_in, const int* in_sizes, int n_in,
                              void* d_out, int out_size) {
    const float* frame1 = (const float*)d_in[0];
    const float* frame2 = (const float*)d_in[1];
    const float* flow   = (const float*)d_in[2];
    float* out = (float*)d_out;

    zero_out_kernel<<<(out_size + 255) / 256, 256>>>(out, out_size);

    const int total = BATCH * HEIGHT * WIDTH;
    const int threads = 256;
    const int blocks = (total + threads - 1) / threads;
    photometric_kernel<<<blocks, threads>>>(frame1, frame2, flow, out);
}